// round 1
// baseline (speedup 1.0000x reference)
#include <cuda_runtime.h>
#include <cstdint>

// Shapes (fixed by the problem)
#define BATCH 16384
#define EDIM  1024   // E == H == 1024
#define GDIM  3072   // 3*H

// Scratch (device globals: allocation-free per harness rules)
__device__ float g_xt[BATCH * EDIM];  // blended input x_t
__device__ float g_h [BATCH * EDIM];  // decayed hidden h

// ---------------------------------------------------------------------------
// helpers
// ---------------------------------------------------------------------------
__device__ __forceinline__ uint32_t f2tf32(float f) {
    uint32_t u;
    asm("cvt.rna.tf32.f32 %0, %1;" : "=r"(u) : "f"(f));
    return u;
}

__device__ __forceinline__ void mma8(float* c, const uint32_t* a, const uint32_t* b) {
    asm volatile(
        "mma.sync.aligned.m16n8k8.row.col.f32.tf32.tf32.f32 "
        "{%0,%1,%2,%3},{%4,%5,%6,%7},{%8,%9},{%0,%1,%2,%3};"
        : "+f"(c[0]), "+f"(c[1]), "+f"(c[2]), "+f"(c[3])
        : "r"(a[0]), "r"(a[1]), "r"(a[2]), "r"(a[3]), "r"(b[0]), "r"(b[1]));
}

__device__ __forceinline__ float sigmoidf_(float x) {
    return 1.0f / (1.0f + __expf(-x));
}

// ---------------------------------------------------------------------------
// Kernel 1: decay GEMM  C = delta @ W^T  (NT, both K-contiguous)
//   mode 0: dx = exp(-relu(C + gx_b));  x_t = m*x + (1-m)*(dx*xl + (1-dx)*xm)
//   mode 1: dh = exp(-relu(C + gh_b));  h   = dh * hs
// Tile: BM=128, BN=64, BK=16. 256 threads, 8 warps (4m x 2n), warp tile 32x32.
// ---------------------------------------------------------------------------
__global__ __launch_bounds__(256)
void decay_gemm(const float* __restrict__ delta,
                const float* __restrict__ w,      // [1024,1024], row j is K-contiguous
                const float* __restrict__ bias,   // [1024]
                const float* __restrict__ x,
                const float* __restrict__ xmask,
                const float* __restrict__ xlast,
                const float* __restrict__ xmean,
                const float* __restrict__ hs,
                int mode)
{
    __shared__ uint32_t As[128][20];  // stride 20 words: conflict-free frag reads
    __shared__ uint32_t Bs[64][20];

    const int tid  = threadIdx.x;
    const int bm   = blockIdx.y * 128;
    const int bn   = blockIdx.x * 64;
    const int warp = tid >> 5, lane = tid & 31;
    const int g    = lane >> 2, tg = lane & 3;
    const int wm   = warp & 3;   // 0..3  -> 32-row band
    const int wn   = warp >> 2;  // 0..1  -> 32-col band

    float acc[2][4][4];
    #pragma unroll
    for (int mt = 0; mt < 2; mt++)
        #pragma unroll
        for (int nt = 0; nt < 4; nt++)
            #pragma unroll
            for (int e = 0; e < 4; e++) acc[mt][nt][e] = 0.0f;

    for (int k0 = 0; k0 < 1024; k0 += 16) {
        // A tile: 128x16 -> 512 float4, 2 per thread
        #pragma unroll
        for (int i = 0; i < 2; i++) {
            int f4  = tid + i * 256;
            int row = f4 >> 2, kc = (f4 & 3) * 4;
            float4 v = *(const float4*)(delta + (bm + row) * 1024 + k0 + kc);
            uint4 t = make_uint4(f2tf32(v.x), f2tf32(v.y), f2tf32(v.z), f2tf32(v.w));
            *(uint4*)&As[row][kc] = t;
        }
        // B tile: 64x16 -> 256 float4, 1 per thread
        {
            int row = tid >> 2, kc = (tid & 3) * 4;
            float4 v = *(const float4*)(w + (bn + row) * 1024 + k0 + kc);
            uint4 t = make_uint4(f2tf32(v.x), f2tf32(v.y), f2tf32(v.z), f2tf32(v.w));
            *(uint4*)&Bs[row][kc] = t;
        }
        __syncthreads();

        #pragma unroll
        for (int ks = 0; ks < 2; ks++) {
            const int kk = ks * 8;
            uint32_t a[2][4];
            #pragma unroll
            for (int mt = 0; mt < 2; mt++) {
                int r0 = wm * 32 + mt * 16;
                a[mt][0] = As[r0 + g][kk + tg];
                a[mt][1] = As[r0 + g + 8][kk + tg];
                a[mt][2] = As[r0 + g][kk + tg + 4];
                a[mt][3] = As[r0 + g + 8][kk + tg + 4];
            }
            #pragma unroll
            for (int nt = 0; nt < 4; nt++) {
                int n0 = wn * 32 + nt * 8;
                uint32_t b[2];
                b[0] = Bs[n0 + g][kk + tg];
                b[1] = Bs[n0 + g][kk + tg + 4];
                #pragma unroll
                for (int mt = 0; mt < 2; mt++) mma8(acc[mt][nt], a[mt], b);
            }
        }
        __syncthreads();
    }

    // epilogue
    #pragma unroll
    for (int mt = 0; mt < 2; mt++) {
        #pragma unroll
        for (int nt = 0; nt < 4; nt++) {
            int row0 = bm + wm * 32 + mt * 16 + g;
            int col0 = bn + wn * 32 + nt * 8 + tg * 2;
            #pragma unroll
            for (int e = 0; e < 4; e++) {
                int i = row0 + (e >> 1) * 8;
                int j = col0 + (e & 1);
                int idx = i * 1024 + j;
                float d = __expf(-fmaxf(acc[mt][nt][e] + bias[j], 0.0f));
                if (mode == 0) {
                    float m  = xmask[idx];
                    float xt = m * x[idx]
                             + (1.0f - m) * (d * xlast[idx] + (1.0f - d) * xmean[idx]);
                    g_xt[idx] = xt;
                } else {
                    g_h[idx] = d * hs[idx];
                }
            }
        }
    }
}

// ---------------------------------------------------------------------------
// Kernel 2: fused 3-gate GEMM over unified K = 3072
//   seg0: A = x_t   (k 0..1023),   B = w_ih rows [0,1024)
//   seg1: A = xmask (k 1024..2047),B = w_ih rows [1024,2048)
//   seg2: A = h     (k 2048..3071),B = w_hh rows [0,1024)
// Accumulators: r (all K), z (all K), i_n (seg0+1), h_n (seg2).
// Tile: BM=128, BN=32 (per gate), BK=16. 256 threads, warp grid 4m x 2n,
// warp tile 32x16 -> 2x2 m16n8 tiles per gate.
// ---------------------------------------------------------------------------
__global__ __launch_bounds__(256)
void gru_gemm(const float* __restrict__ xmask,
              const float* __restrict__ w_ih,   // [2048, 3072] row-major
              const float* __restrict__ b_ih,   // [3072]
              const float* __restrict__ w_hh,   // [1024, 3072] row-major
              const float* __restrict__ b_hh,   // [3072]
              float* __restrict__ out)
{
    __shared__ uint32_t As[128][20];
    __shared__ uint32_t Bs[3][32][20];  // [gate][n][k], transposed on load

    const int tid  = threadIdx.x;
    const int bm   = blockIdx.y * 128;
    const int bn   = blockIdx.x * 32;
    const int warp = tid >> 5, lane = tid & 31;
    const int g    = lane >> 2, tg = lane & 3;
    const int wm   = warp & 3;   // 32-row band
    const int wn   = warp >> 2;  // 16-col band

    float aR[2][2][4], aZ[2][2][4], aIN[2][2][4], aHN[2][2][4];
    #pragma unroll
    for (int mt = 0; mt < 2; mt++)
        #pragma unroll
        for (int nt = 0; nt < 2; nt++)
            #pragma unroll
            for (int e = 0; e < 4; e++) {
                aR[mt][nt][e] = 0.0f; aZ[mt][nt][e] = 0.0f;
                aIN[mt][nt][e] = 0.0f; aHN[mt][nt][e] = 0.0f;
            }

    #pragma unroll 1
    for (int seg = 0; seg < 3; seg++) {
        const float* Aseg = (seg == 0) ? g_xt : ((seg == 1) ? xmask : g_h);
        const float* Wseg = (seg == 2) ? w_hh : w_ih;
        const int wrow_off = (seg == 1) ? 1024 : 0;

        #pragma unroll 1
        for (int k0 = 0; k0 < 1024; k0 += 16) {
            // A tile: 128x16 -> 512 float4, 2 per thread
            #pragma unroll
            for (int i = 0; i < 2; i++) {
                int f4  = tid + i * 256;
                int row = f4 >> 2, kc = (f4 & 3) * 4;
                float4 v = *(const float4*)(Aseg + (bm + row) * 1024 + k0 + kc);
                uint4 t = make_uint4(f2tf32(v.x), f2tf32(v.y), f2tf32(v.z), f2tf32(v.w));
                *(uint4*)&As[row][kc] = t;
            }
            // B tiles: 3 gates x 16k x 32n = 384 float4 jobs (load n-contig,
            // store transposed [n][k])
            #pragma unroll
            for (int t = tid; t < 384; t += 256) {
                int gate = t >> 7;
                int r    = t & 127;
                int kr   = r >> 3;      // 0..15
                int nq   = r & 7;       // float4 along n
                float4 v = *(const float4*)(Wseg + (wrow_off + k0 + kr) * 3072
                                            + gate * 1024 + bn + nq * 4);
                Bs[gate][nq * 4 + 0][kr] = f2tf32(v.x);
                Bs[gate][nq * 4 + 1][kr] = f2tf32(v.y);
                Bs[gate][nq * 4 + 2][kr] = f2tf32(v.z);
                Bs[gate][nq * 4 + 3][kr] = f2tf32(v.w);
            }
            __syncthreads();

            #pragma unroll
            for (int ks = 0; ks < 2; ks++) {
                const int kk = ks * 8;
                uint32_t a[2][4];
                #pragma unroll
                for (int mt = 0; mt < 2; mt++) {
                    int r0 = wm * 32 + mt * 16;
                    a[mt][0] = As[r0 + g][kk + tg];
                    a[mt][1] = As[r0 + g + 8][kk + tg];
                    a[mt][2] = As[r0 + g][kk + tg + 4];
                    a[mt][3] = As[r0 + g + 8][kk + tg + 4];
                }
                #pragma unroll
                for (int nt = 0; nt < 2; nt++) {
                    int n0 = wn * 16 + nt * 8;
                    uint32_t bR[2] = { Bs[0][n0 + g][kk + tg], Bs[0][n0 + g][kk + tg + 4] };
                    uint32_t bZ[2] = { Bs[1][n0 + g][kk + tg], Bs[1][n0 + g][kk + tg + 4] };
                    uint32_t bN[2] = { Bs[2][n0 + g][kk + tg], Bs[2][n0 + g][kk + tg + 4] };
                    #pragma unroll
                    for (int mt = 0; mt < 2; mt++) {
                        mma8(aR[mt][nt], a[mt], bR);
                        mma8(aZ[mt][nt], a[mt], bZ);
                        if (seg < 2) mma8(aIN[mt][nt], a[mt], bN);
                        else         mma8(aHN[mt][nt], a[mt], bN);
                    }
                }
            }
            __syncthreads();
        }
    }

    // GRU epilogue
    #pragma unroll
    for (int mt = 0; mt < 2; mt++) {
        #pragma unroll
        for (int nt = 0; nt < 2; nt++) {
            int row0 = bm + wm * 32 + mt * 16 + g;
            int col0 = bn + wn * 16 + nt * 8 + tg * 2;
            #pragma unroll
            for (int e = 0; e < 4; e++) {
                int i = row0 + (e >> 1) * 8;
                int j = col0 + (e & 1);
                float r = sigmoidf_(aR[mt][nt][e] + b_ih[j] + b_hh[j]);
                float z = sigmoidf_(aZ[mt][nt][e] + b_ih[1024 + j] + b_hh[1024 + j]);
                float n = tanhf(aIN[mt][nt][e] + b_ih[2048 + j]
                                + r * (aHN[mt][nt][e] + b_hh[2048 + j]));
                float hv = g_h[i * 1024 + j];
                out[i * 1024 + j] = (1.0f - z) * n + z * hv;
            }
        }
    }
}

// ---------------------------------------------------------------------------
// launch
// ---------------------------------------------------------------------------
extern "C" void kernel_launch(void* const* d_in, const int* in_sizes, int n_in,
                              void* d_out, int out_size)
{
    const float* x     = (const float*)d_in[0];
    const float* xmask = (const float*)d_in[1];
    const float* delta = (const float*)d_in[2];
    const float* xlast = (const float*)d_in[3];
    const float* xmean = (const float*)d_in[4];
    const float* hs    = (const float*)d_in[5];
    const float* gx_w  = (const float*)d_in[6];
    const float* gx_b  = (const float*)d_in[7];
    const float* gh_w  = (const float*)d_in[8];
    const float* gh_b  = (const float*)d_in[9];
    const float* w_ih  = (const float*)d_in[10];
    const float* b_ih  = (const float*)d_in[11];
    const float* w_hh  = (const float*)d_in[12];
    const float* b_hh  = (const float*)d_in[13];
    float* out = (float*)d_out;

    dim3 grid1(1024 / 64, BATCH / 128);      // 16 x 128
    decay_gemm<<<grid1, 256>>>(delta, gx_w, gx_b, x, xmask, xlast, xmean, hs, 0);
    decay_gemm<<<grid1, 256>>>(delta, gh_w, gh_b, x, xmask, xlast, xmean, hs, 1);

    dim3 grid2(1024 / 32, BATCH / 128);      // 32 x 128
    gru_gemm<<<grid2, 256>>>(xmask, w_ih, b_ih, w_hh, b_hh, out);
}